// round 13
// baseline (speedup 1.0000x reference)
#include <cuda_runtime.h>
#include <cuda_bf16.h>
#include <cstdint>

#define Bn   128
#define Sn   512
#define Ln   64
#define NPAIRS ((Bn-1)*Sn)       // 65024
#define PPB2 256                 // pairs per block (2 concurrent tiles of 128)
#define NBLK2 (NPAIRS/PPB2)      // 254
#define EPITCH 132               // est column pitch (floats)
#define TP 68                    // sT pitch in floats

#define LOG2E 1.4426950408889634f
#define LN2f  0.6931471805599453f

// smem layout (bytes)
#define SO_ST    0
#define SO_EST0  17408
#define SO_EST1  51200
#define SO_FLAGS 84992
#define SO_SSC   86016
#define SO_SCNT  86048
#define SO_SLAST 86064
#define SMEM_TOTAL 86144

// Zero-initialized at module load; finalizer block resets after use.
__device__ float    g_alpha[Ln];
__device__ double   g_score;
__device__ unsigned g_done;

__device__ __forceinline__ float ex2f(float x){ float y; asm("ex2.approx.f32 %0, %1;" : "=f"(y) : "f"(x)); return y; }
__device__ __forceinline__ float lg2f_(float x){ float y; asm("lg2.approx.f32 %0, %1;" : "=f"(y) : "f"(x)); return y; }
__device__ __forceinline__ void ffma2(unsigned long long& d, unsigned long long a, unsigned long long b){
    asm("fma.rn.f32x2 %0, %1, %2, %0;" : "+l"(d) : "l"(a), "l"(b));
}
__device__ __forceinline__ unsigned long long pack2(float v){
    unsigned long long r; asm("mov.b64 %0, {%1, %1};" : "=l"(r) : "f"(v)); return r;
}

// One 128-pair tile mainloop; accumulates masked log2 sums into csum.
__device__ __forceinline__ void tile_main(const float* __restrict__ sT,
                                          const float* __restrict__ est,
                                          const float* __restrict__ flags,
                                          int tl, float csum[4])
{
    const int i4 = tl & 15;
    const int pg = tl >> 4;
    unsigned long long acc[4][4];
    #pragma unroll
    for (int k = 0; k < 4; ++k)
        #pragma unroll
        for (int m = 0; m < 4; ++m) acc[k][m] = 0ull;

    const float4*     sT4 = (const float4*)sT;                 // [j*17 + i4]
    const ulonglong2* pE  = (const ulonglong2*)(est) + pg*2;   // step 33/j

    #pragma unroll 8
    for (int j = 0; j < 64; ++j){
        float4 tv = sT4[j*17 + i4];
        ulonglong2 ea = pE[j*33];
        ulonglong2 eb = pE[j*33 + 1];
        unsigned long long tp[4] = {pack2(tv.x), pack2(tv.y), pack2(tv.z), pack2(tv.w)};
        unsigned long long ep[4] = {ea.x, ea.y, eb.x, eb.y};
        #pragma unroll
        for (int k = 0; k < 4; ++k){
            ffma2(acc[k][0], tp[k], ep[0]);
            ffma2(acc[k][1], tp[k], ep[1]);
            ffma2(acc[k][2], tp[k], ep[2]);
            ffma2(acc[k][3], tp[k], ep[3]);
        }
    }
    #pragma unroll
    for (int m = 0; m < 4; ++m){
        float f0 = flags[(pg << 3) + 2*m];
        float f1 = flags[(pg << 3) + 2*m + 1];
        #pragma unroll
        for (int k = 0; k < 4; ++k){
            float lo = __uint_as_float((unsigned)(acc[k][m] & 0xffffffffull));
            float hi = __uint_as_float((unsigned)(acc[k][m] >> 32));
            csum[k] += f0 * lg2f_(lo) + f1 * lg2f_(hi);
        }
    }
}

// ---------------------------------------------------------------------------
// Mega kernel.  254 blocks x 512 threads: two concurrent 128-pair tiles.
// ---------------------------------------------------------------------------
__global__ __launch_bounds__(512, 2) void mega_kernel(
    const float* __restrict__ emit,  const int* __restrict__ labels,
    const int*   __restrict__ mask,  const float* __restrict__ trans,
    const float* __restrict__ strans,const float* __restrict__ etrans,
    float* __restrict__ out)
{
    extern __shared__ char smem[];
    float* sT    = (float*)(smem + SO_ST);
    float* flags = (float*)(smem + SO_FLAGS);
    float* ssc   = (float*)(smem + SO_SSC);
    int*   scnt  = (int*)  (smem + SO_SCNT);
    unsigned* slast = (unsigned*)(smem + SO_SLAST);

    const int t   = threadIdx.x;
    const int bx  = blockIdx.x;
    const int grp = t >> 8;            // warp group 0/1 -> tile 0/1
    const int tl  = t & 255;
    const int pb  = bx * PPB2;         // block pair base
    float* estg = (float*)(smem + (grp ? SO_EST1 : SO_EST0));

    // ======== front-issue scattered score gathers ========
    float sv = 0.f;
    int   mk_v = 0;
    if (t < 256){
        int p = pb + t;                // pair index
        int g = p + Sn;
        int l  = labels[g];
        int lp = labels[g - 1];
        float em_v = emit[(size_t)g*Ln + l];
        float tr_v = trans[lp*Ln + l];
        mk_v = mask[g];
        if (mk_v){ sv = em_v; if (p & 511) sv += tr_v; }
    } else if (bx < 2){
        int g2 = bx*256 + (t - 256);   // b=0 region, 0..511
        int l2 = labels[g2];
        int g2m = (g2 > 0) ? g2 - 1 : 0;
        float e2v = emit[(size_t)g2*Ln + l2];
        float t2v = trans[labels[g2m]*Ln + l2];
        if (mask[g2]){ sv = e2v; if (g2 & 511) sv += t2v; }
    }
    int4 mker = make_int4(0,0,0,0);
    if (bx < Bn && t >= 256 && t < 384)
        mker = ((const int4*)(mask + bx*Sn))[t - 256];

    // ======== sT build (shared by both groups) ========
    #pragma unroll
    for (int it = 0; it < 8; ++it){
        int o = t + it*512;            // 0..4095
        int i = o >> 6, j = o & 63;
        sT[j*TP + i] = ex2f(trans[i*64 + j] * LOG2E);
    }
    // ======== est fill: each group its own tile ========
    {
        const float4* e4 = (const float4*)(emit + (size_t)(pb + grp*128 + Sn)*Ln);
        #pragma unroll
        for (int it = 0; it < 8; ++it){
            int v = tl + it*256;       // 0..2047 float4
            float4 x = e4[v];
            int p  = v >> 4;
            int j0 = (v & 15) * 4;
            estg[(j0  )*EPITCH + p] = ex2f(x.x * LOG2E);
            estg[(j0+1)*EPITCH + p] = ex2f(x.y * LOG2E);
            estg[(j0+2)*EPITCH + p] = ex2f(x.z * LOG2E);
            estg[(j0+3)*EPITCH + p] = ex2f(x.w * LOG2E);
        }
    }
    if (t < 256) flags[t] = mk_v ? 1.0f : 0.0f;

    // ======== score reductions ========
    {
        float v = sv;
        #pragma unroll
        for (int o = 16; o; o >>= 1) v += __shfl_down_sync(0xffffffffu, v, o);
        if ((t & 31) == 0) ssc[t >> 5] = v;    // 16 warps
    }
    if (bx < Bn && t >= 256 && t < 384){
        int tt = t - 256;
        int cnt = (mker.x!=0) + (mker.y!=0) + (mker.z!=0) + (mker.w!=0);
        #pragma unroll
        for (int o = 16; o; o >>= 1) cnt += __shfl_down_sync(0xffffffffu, cnt, o);
        if ((tt & 31) == 0) scnt[tt >> 5] = cnt;
    }
    __syncthreads();

    if (t == 0){
        double tot = 0.0;
        #pragma unroll
        for (int i = 0; i < 16; ++i) tot += (double)ssc[i];
        if (bx < Bn){
            int c = scnt[0] + scnt[1] + scnt[2] + scnt[3];
            int end = c - 1; if (end < 0) end = 0;
            const int* lab = labels + bx*Sn;
            tot += (double)strans[lab[0]] + (double)etrans[lab[end]];
        }
        atomicAdd(&g_score, tot);
    }

    // ======== mainloop (both groups run concurrently) ========
    float csum[4] = {0.f, 0.f, 0.f, 0.f};
    tile_main(sT, estg, flags + grp*128, tl, csum);

    // ======== reduction ========
    __syncthreads();                   // all groups done reading est
    float* red = estg;                 // each group reuses its own est
    const int i4 = tl & 15, pg = tl >> 4;
    #pragma unroll
    for (int k = 0; k < 4; ++k) red[pg*64 + (i4 << 2) + k] = csum[k];
    __syncthreads();

    if (tl < Ln){
        float s = 0.f;
        #pragma unroll
        for (int gi = 0; gi < 16; ++gi) s += red[gi*64 + tl];
        atomicAdd(&g_alpha[tl], s * LN2f);
    }

    // ======== last-block finalize + state reset ========
    __threadfence();
    if (t == 0){
        unsigned prev = atomicAdd(&g_done, 1u);
        *slast = (prev == NBLK2 - 1) ? 1u : 0u;
    }
    __syncthreads();
    if (*slast){
        float* fr = (float*)(smem + SO_EST0);
        float a = -1e30f;
        if (t < Ln) a = g_alpha[t] + emit[t];          // + emit[0,0,:]
        float m = a;
        #pragma unroll
        for (int o = 16; o; o >>= 1) m = fmaxf(m, __shfl_xor_sync(0xffffffffu, m, o));
        if ((t & 31) == 0) fr[t >> 5] = m;
        __syncthreads();
        m = fr[0];
        #pragma unroll
        for (int i = 1; i < 16; ++i) m = fmaxf(m, fr[i]);
        float e = (t < Ln) ? ex2f((a - m) * LOG2E) : 0.f;
        #pragma unroll
        for (int o = 16; o; o >>= 1) e += __shfl_xor_sync(0xffffffffu, e, o);
        if ((t & 31) == 0) fr[16 + (t >> 5)] = e;
        __syncthreads();
        if (t == 0){
            float es = 0.f;
            #pragma unroll
            for (int i = 0; i < 16; ++i) es += fr[16 + i];
            double logZ = (double)m + (double)(LN2f * lg2f_(es));
            out[0] = (float)((logZ - g_score) / (double)Bn);
        }
        __syncthreads();
        if (t < Ln)  g_alpha[t] = 0.0f;
        if (t == 0){ g_score = 0.0; g_done = 0u; }
    }
}

// ---------------------------------------------------------------------------
extern "C" void kernel_launch(void* const* d_in, const int* in_sizes, int n_in,
                              void* d_out, int out_size)
{
    const float* emit   = (const float*)d_in[0];
    const int*   labels = (const int*)d_in[1];
    const int*   mask   = (const int*)d_in[2];
    const float* trans  = (const float*)d_in[3];
    const float* strans = (const float*)d_in[4];
    const float* etrans = (const float*)d_in[5];
    float* out = (float*)d_out;

    // Idempotent; first (pre-capture) call takes effect. Ignore errors.
    static_assert(SMEM_TOTAL <= 227*1024, "smem");
    cudaFuncSetAttribute(mega_kernel, cudaFuncAttributeMaxDynamicSharedMemorySize, SMEM_TOTAL);

    mega_kernel<<<NBLK2, 512, SMEM_TOTAL>>>(emit, labels, mask, trans, strans, etrans, out);
}

// round 14
// speedup vs baseline: 1.1313x; 1.1313x over previous
#include <cuda_runtime.h>
#include <cuda_fp16.h>
#include <cstdint>

#define Bn   128
#define Sn   512
#define Ln   64
#define NPAIRS ((Bn-1)*Sn)       // 65024
#define NT   (NPAIRS/128)        // 508 tiles of 128 pairs
#define NBLKG 592                // 4 blocks/SM x 148
#define EP   132                 // est row pitch in h2 units (per j2 row: 128 p + pad)
#define TP2  68                  // sT2 row pitch in h2 units

#define LOG2E 1.4426950408889634f
#define LN2f  0.6931471805599453f

// Zero-initialized at module load; finalizer resets after use (graph replay safe).
__device__ float    g_alpha[Ln];
__device__ double   g_score;
__device__ unsigned g_done;
__device__ unsigned g_tick;

__device__ __forceinline__ float ex2f(float x){ float y; asm("ex2.approx.f32 %0, %1;" : "=f"(y) : "f"(x)); return y; }
__device__ __forceinline__ float lg2f_(float x){ float y; asm("lg2.approx.f32 %0, %1;" : "=f"(y) : "f"(x)); return y; }
// pack two f32 into f16x2: lo -> .lo, hi -> .hi  (PTX: first src -> upper half)
__device__ __forceinline__ unsigned pk2(float lo, float hi){
    unsigned r; asm("cvt.rn.f16x2.f32 %0, %1, %2;" : "=r"(r) : "f"(hi), "f"(lo)); return r;
}
__device__ __forceinline__ void hfma2(unsigned& d, unsigned a, unsigned b){
    asm("fma.rn.f16x2 %0, %1, %2, %0;" : "+r"(d) : "r"(a), "r"(b));
}
__device__ __forceinline__ float h2sum(unsigned h){
    __half2 v = *reinterpret_cast<__half2*>(&h);
    float2 f = __half22float2(v);
    return f.x + f.y;
}

// ---------------------------------------------------------------------------
// Mega kernel: 592 blocks x 256 threads.  Dynamic tile tickets (508 tiles).
// fp16x2 HFMA2 mainloop packed over (j, j+1).
// ---------------------------------------------------------------------------
__global__ __launch_bounds__(256, 4) void mega_kernel(
    const float* __restrict__ emit,  const int* __restrict__ labels,
    const int*   __restrict__ mask,  const float* __restrict__ trans,
    const float* __restrict__ strans,const float* __restrict__ etrans,
    float* __restrict__ out)
{
    __shared__ __align__(16) unsigned sT2[32*TP2];   // [j2*68 + i] = (expT[i][2j2], expT[i][2j2+1])
    __shared__ __align__(16) unsigned est[32*EP];    // [j2*132 + p] = (e[p][2j2], e[p][2j2+1])
    __shared__ float flags[128];
    __shared__ float ssc[8];
    __shared__ int   scnt[4];
    __shared__ unsigned stick, slast;

    const int t  = threadIdx.x;
    const int i4 = t & 15;            // i = 4*i4 .. 4*i4+3
    const int pg = t >> 4;            // p = 8*pg .. 8*pg+7

    float csum[4] = {0.f, 0.f, 0.f, 0.f};
    bool built = false;

    for (;;){
        if (t == 0) stick = atomicAdd(&g_tick, 1u);
        __syncthreads();
        const unsigned tk = stick;
        if (tk >= NT) break;
        const int p0 = (int)tk * 128;

        // ---- one-time sT2 build (only blocks that got work) ----
        if (!built){
            built = true;
            #pragma unroll
            for (int it = 0; it < 8; ++it){
                int o = t + it*256;            // 0..2047
                int i = o >> 5, j2 = o & 31;
                float2 tv = *(const float2*)(trans + i*64 + 2*j2);
                sT2[j2*TP2 + i] = pk2(ex2f(tv.x*LOG2E), ex2f(tv.y*LOG2E));
            }
        }

        // ---- score gathers for this tile ----
        float sv = 0.f;
        if (t < 128){
            int g = p0 + Sn + t;               // global (b,s) row
            int l  = labels[g];
            int lp = labels[g - 1];
            float em_v = emit[(size_t)g*Ln + l];
            float tr_v = trans[lp*Ln + l];
            int mk = mask[g];
            flags[t] = mk ? 1.0f : 0.0f;
            if (mk){ sv = em_v; if (g & 511) sv += tr_v; }
        } else if (tk < 4){
            int g2 = (int)tk*128 + (t - 128);  // b=0 rows 0..511
            int l2 = labels[g2];
            int g2m = (g2 > 0) ? g2 - 1 : 0;
            float e2v = emit[(size_t)g2*Ln + l2];
            float t2v = trans[labels[g2m]*Ln + l2];
            if (mask[g2]){ sv = e2v; if (g2 & 511) sv += t2v; }
        }
        if (tk < Bn && t >= 128){
            const int4 m = ((const int4*)(mask + (int)tk*Sn))[t - 128];
            int cnt = (m.x!=0) + (m.y!=0) + (m.z!=0) + (m.w!=0);
            #pragma unroll
            for (int o = 16; o; o >>= 1) cnt += __shfl_down_sync(0xffffffffu, cnt, o);
            if (((t - 128) & 31) == 0) scnt[(t - 128) >> 5] = cnt;
        }
        {
            float v = sv;
            #pragma unroll
            for (int o = 16; o; o >>= 1) v += __shfl_down_sync(0xffffffffu, v, o);
            if ((t & 31) == 0) ssc[t >> 5] = v;
        }

        // ---- est fill: lane-linear LDG, ex2, within-thread j-pair pack ----
        {
            const float4* e4 = (const float4*)(emit + (size_t)(p0 + Sn)*Ln);
            #pragma unroll
            for (int it = 0; it < 8; ++it){
                int v = t + it*256;            // 0..2047 float4
                float4 x = e4[v];
                int p  = v >> 4;
                int j2 = (v & 15) * 2;         // j0/2
                est[(j2  )*EP + p] = pk2(ex2f(x.x*LOG2E), ex2f(x.y*LOG2E));
                est[(j2+1)*EP + p] = pk2(ex2f(x.z*LOG2E), ex2f(x.w*LOG2E));
            }
        }
        __syncthreads();

        if (t == 0){
            double tot = 0.0;
            #pragma unroll
            for (int i = 0; i < 8; ++i) tot += (double)ssc[i];
            if (tk < Bn){
                int c = scnt[0] + scnt[1] + scnt[2] + scnt[3];
                int end = c - 1; if (end < 0) end = 0;
                const int* lab = labels + (int)tk*Sn;
                tot += (double)strans[lab[0]] + (double)etrans[lab[end]];
            }
            atomicAdd(&g_score, tot);
        }

        // ---- mainloop: HFMA2 packed over (j, j+1) ----
        unsigned acc[4][8];
        #pragma unroll
        for (int k = 0; k < 4; ++k)
            #pragma unroll
            for (int m = 0; m < 8; ++m) acc[k][m] = 0u;

        const uint4* sTv = (const uint4*)sT2;       // [j2*17 + i4]
        const uint4* eV  = (const uint4*)est;       // [j2*33 + pg*2]

        #pragma unroll 8
        for (int j2 = 0; j2 < 32; ++j2){
            uint4 tv = sTv[j2*17 + i4];             // i = 4i4..+3
            uint4 ea = eV[j2*33 + pg*2];            // p = 8pg..+3
            uint4 eb = eV[j2*33 + pg*2 + 1];        // p = 8pg+4..+7
            unsigned tp[4] = {tv.x, tv.y, tv.z, tv.w};
            unsigned ep[8] = {ea.x, ea.y, ea.z, ea.w, eb.x, eb.y, eb.z, eb.w};
            #pragma unroll
            for (int k = 0; k < 4; ++k){
                #pragma unroll
                for (int m = 0; m < 8; ++m) hfma2(acc[k][m], tp[k], ep[m]);
            }
        }

        // ---- epilogue: c = lg2(lo+hi), masked accumulate ----
        #pragma unroll
        for (int m = 0; m < 8; ++m){
            float f = flags[pg*8 + m];
            #pragma unroll
            for (int k = 0; k < 4; ++k)
                csum[k] += f * lg2f_(h2sum(acc[k][m]));
        }
        // loop back: ticket-grab barrier protects est/flags reuse
    }

    // ---- block reduction of csum into g_alpha ----
    __syncthreads();
    float* red = (float*)est;
    #pragma unroll
    for (int k = 0; k < 4; ++k) red[pg*64 + i4*4 + k] = csum[k];
    __syncthreads();
    if (t < Ln){
        float s = 0.f;
        #pragma unroll
        for (int gi = 0; gi < 16; ++gi) s += red[gi*64 + t];
        atomicAdd(&g_alpha[t], s * LN2f);
    }

    // ---- last-block finalize + state reset ----
    __threadfence();
    if (t == 0){
        unsigned prev = atomicAdd(&g_done, 1u);
        slast = (prev == NBLKG - 1) ? 1u : 0u;
    }
    __syncthreads();
    if (slast){
        float a = -1e30f;
        if (t < Ln) a = g_alpha[t] + emit[t];      // + emit[0,0,:]
        float m = a;
        #pragma unroll
        for (int o = 16; o; o >>= 1) m = fmaxf(m, __shfl_xor_sync(0xffffffffu, m, o));
        if ((t & 31) == 0) red[t >> 5] = m;
        __syncthreads();
        m = fmaxf(red[0], fmaxf(red[1], fmaxf(red[2], fmaxf(red[3],
              fmaxf(red[4], fmaxf(red[5], fmaxf(red[6], red[7])))))));
        float e = (t < Ln) ? ex2f((a - m) * LOG2E) : 0.f;
        #pragma unroll
        for (int o = 16; o; o >>= 1) e += __shfl_xor_sync(0xffffffffu, e, o);
        if ((t & 31) == 0) red[8 + (t >> 5)] = e;
        __syncthreads();
        if (t == 0){
            float es = 0.f;
            #pragma unroll
            for (int i = 0; i < 8; ++i) es += red[8 + i];
            double logZ = (double)m + (double)(LN2f * lg2f_(es));
            out[0] = (float)((logZ - g_score) / (double)Bn);
        }
        __syncthreads();
        if (t < Ln)  g_alpha[t] = 0.0f;
        if (t == 0){ g_score = 0.0; g_done = 0u; g_tick = 0u; }
    }
}

// ---------------------------------------------------------------------------
extern "C" void kernel_launch(void* const* d_in, const int* in_sizes, int n_in,
                              void* d_out, int out_size)
{
    const float* emit   = (const float*)d_in[0];
    const int*   labels = (const int*)d_in[1];
    const int*   mask   = (const int*)d_in[2];
    const float* trans  = (const float*)d_in[3];
    const float* strans = (const float*)d_in[4];
    const float* etrans = (const float*)d_in[5];
    float* out = (float*)d_out;

    mega_kernel<<<NBLKG, 256>>>(emit, labels, mask, trans, strans, etrans, out);
}

// round 15
// speedup vs baseline: 1.1825x; 1.0452x over previous
#include <cuda_runtime.h>
#include <cuda_fp16.h>
#include <cstdint>

#define Bn   128
#define Sn   512
#define Ln   64
#define NPAIRS ((Bn-1)*Sn)       // 65024
#define NBLK (NPAIRS/128)        // 508 blocks, one 128-pair tile each
#define EP   132                 // est row pitch (h2 units)
#define TP2  68                  // sT2 row pitch (h2 units)

#define LOG2E 1.4426950408889634f
#define LN2f  0.6931471805599453f

// Zero-initialized at module load; finalizer resets after use (replay safe).
__device__ float    g_alpha[Ln];
__device__ double   g_score;
__device__ unsigned g_done;

__device__ __forceinline__ float ex2f(float x){ float y; asm("ex2.approx.f32 %0, %1;" : "=f"(y) : "f"(x)); return y; }
__device__ __forceinline__ float lg2f_(float x){ float y; asm("lg2.approx.f32 %0, %1;" : "=f"(y) : "f"(x)); return y; }
// pack two f32 into f16x2 (first asm src -> upper half)
__device__ __forceinline__ unsigned pk2(float lo, float hi){
    unsigned r; asm("cvt.rn.f16x2.f32 %0, %1, %2;" : "=r"(r) : "f"(hi), "f"(lo)); return r;
}
__device__ __forceinline__ unsigned ex2h2(unsigned x){
    unsigned r; asm("ex2.approx.f16x2 %0, %1;" : "=r"(r) : "r"(x)); return r;
}
__device__ __forceinline__ void hfma2(unsigned& d, unsigned a, unsigned b){
    asm("fma.rn.f16x2 %0, %1, %2, %0;" : "+r"(d) : "r"(a), "r"(b));
}
__device__ __forceinline__ float h2sum(unsigned h){
    __half2 v = *reinterpret_cast<__half2*>(&h);
    float2 f = __half22float2(v);
    return f.x + f.y;
}

// ---------------------------------------------------------------------------
// Mega kernel: 508 blocks x 256 threads, one 128-pair tile per block.
// ---------------------------------------------------------------------------
__global__ __launch_bounds__(256, 4) void mega_kernel(
    const float* __restrict__ emit,  const int* __restrict__ labels,
    const int*   __restrict__ mask,  const float* __restrict__ trans,
    const float* __restrict__ strans,const float* __restrict__ etrans,
    float* __restrict__ out)
{
    __shared__ __align__(16) unsigned sT2[32*TP2];   // [j2*68 + i]
    __shared__ __align__(16) unsigned est[32*EP];    // [j2*132 + p]
    __shared__ float flags[128];
    __shared__ float ssc[8];
    __shared__ int   scnt[4];
    __shared__ unsigned slast;

    const int t  = threadIdx.x;
    const int bx = blockIdx.x;
    const int p0 = bx * 128;
    const int i4 = t & 15;            // i = 4*i4 .. 4*i4+3
    const int pg = t >> 4;            // p = 8*pg .. 8*pg+7

    // ======== front-issue scattered gathers (consumed AFTER mainloop) ========
    float em_v = 0.f, tr_v = 0.f;
    int   mk = 0, g = 0;
    if (t < 128){
        g = p0 + Sn + t;
        int l  = labels[g];
        int lp = labels[g - 1];
        em_v = emit[(size_t)g*Ln + l];
        tr_v = trans[lp*Ln + l];
        mk   = mask[g];
    } else if (bx < 4){
        g = bx*128 + (t - 128);            // b=0 rows 0..511
        int l  = labels[g];
        int lp = labels[(g > 0) ? g - 1 : 0];
        em_v = emit[(size_t)g*Ln + l];
        tr_v = trans[lp*Ln + l];
        mk   = mask[g];
    }
    int4 mker = make_int4(0,0,0,0);
    if (bx < Bn && t >= 128) mker = ((const int4*)(mask + bx*Sn))[t - 128];

    // ======== sT2 build: coalesced LDG, f16x2 ex2 ========
    #pragma unroll
    for (int it = 0; it < 8; ++it){
        int o = t + it*256;            // 0..2047
        int i = o >> 5, j2 = o & 31;
        float2 tv = *(const float2*)(trans + i*64 + 2*j2);
        sT2[j2*TP2 + i] = ex2h2(pk2(tv.x*LOG2E, tv.y*LOG2E));
    }
    // ======== est fill: lane-linear LDG, f16x2 ex2, j-pair pack ========
    {
        const float4* e4 = (const float4*)(emit + (size_t)(p0 + Sn)*Ln);
        #pragma unroll
        for (int it = 0; it < 8; ++it){
            int v = t + it*256;        // 0..2047 float4
            float4 x = e4[v];
            int p  = v >> 4;
            int j2 = (v & 15) * 2;
            est[(j2  )*EP + p] = ex2h2(pk2(x.x*LOG2E, x.y*LOG2E));
            est[(j2+1)*EP + p] = ex2h2(pk2(x.z*LOG2E, x.w*LOG2E));
        }
    }
    if (t < 128) flags[t] = mk ? 1.0f : 0.0f;
    __syncthreads();

    // ======== mainloop: HFMA2 packed over (j, j+1) ========
    unsigned acc[4][8];
    #pragma unroll
    for (int k = 0; k < 4; ++k)
        #pragma unroll
        for (int m = 0; m < 8; ++m) acc[k][m] = 0u;

    const uint4* sTv = (const uint4*)sT2;       // [j2*17 + i4]
    const uint4* eV  = (const uint4*)est;       // [j2*33 + pg*2]

    #pragma unroll 8
    for (int j2 = 0; j2 < 32; ++j2){
        uint4 tv = sTv[j2*17 + i4];
        uint4 ea = eV[j2*33 + pg*2];
        uint4 eb = eV[j2*33 + pg*2 + 1];
        unsigned tp[4] = {tv.x, tv.y, tv.z, tv.w};
        unsigned ep[8] = {ea.x, ea.y, ea.z, ea.w, eb.x, eb.y, eb.z, eb.w};
        #pragma unroll
        for (int k = 0; k < 4; ++k){
            #pragma unroll
            for (int m = 0; m < 8; ++m) hfma2(acc[k][m], tp[k], ep[m]);
        }
    }

    // ======== epilogue: log2 of 4-way products (8 lg2/thread) ========
    float csum[4] = {0.f, 0.f, 0.f, 0.f};
    {
        bool f[8];
        #pragma unroll
        for (int m = 0; m < 8; ++m) f[m] = flags[pg*8 + m] != 0.0f;
        #pragma unroll
        for (int k = 0; k < 4; ++k){
            float a0 = f[0] ? h2sum(acc[k][0]) : 1.0f;
            float a1 = f[1] ? h2sum(acc[k][1]) : 1.0f;
            float a2 = f[2] ? h2sum(acc[k][2]) : 1.0f;
            float a3 = f[3] ? h2sum(acc[k][3]) : 1.0f;
            float b0 = f[4] ? h2sum(acc[k][4]) : 1.0f;
            float b1 = f[5] ? h2sum(acc[k][5]) : 1.0f;
            float b2 = f[6] ? h2sum(acc[k][6]) : 1.0f;
            float b3 = f[7] ? h2sum(acc[k][7]) : 1.0f;
            csum[k] = lg2f_((a0*a1)*(a2*a3)) + lg2f_((b0*b1)*(b2*b3));
        }
    }

    // ======== score consume + reduce (gather latency long hidden) ========
    {
        float v = 0.f;
        if (mk){
            v = em_v;
            if (g & 511) v += tr_v;    // s != 0
        }
        #pragma unroll
        for (int o = 16; o; o >>= 1) v += __shfl_down_sync(0xffffffffu, v, o);
        if ((t & 31) == 0) ssc[t >> 5] = v;
    }
    if (bx < Bn && t >= 128){
        int cnt = (mker.x!=0) + (mker.y!=0) + (mker.z!=0) + (mker.w!=0);
        #pragma unroll
        for (int o = 16; o; o >>= 1) cnt += __shfl_down_sync(0xffffffffu, cnt, o);
        if (((t - 128) & 31) == 0) scnt[(t - 128) >> 5] = cnt;
    }

    // ======== block reduction ========
    __syncthreads();
    float* red = (float*)est;
    #pragma unroll
    for (int k = 0; k < 4; ++k) red[pg*64 + i4*4 + k] = csum[k];
    __syncthreads();

    if (t == 0){
        double tot = 0.0;
        #pragma unroll
        for (int i = 0; i < 8; ++i) tot += (double)ssc[i];
        if (bx < Bn){
            int c = scnt[0] + scnt[1] + scnt[2] + scnt[3];
            int end = c - 1; if (end < 0) end = 0;
            const int* lab = labels + bx*Sn;
            tot += (double)strans[lab[0]] + (double)etrans[lab[end]];
        }
        atomicAdd(&g_score, tot);
    }
    if (t < Ln){
        float s = 0.f;
        #pragma unroll
        for (int gi = 0; gi < 16; ++gi) s += red[gi*64 + t];
        atomicAdd(&g_alpha[t], s * LN2f);
    }

    // ======== last-block finalize + state reset ========
    __threadfence();
    __syncthreads();
    if (t == 0){
        unsigned prev = atomicAdd(&g_done, 1u);
        slast = (prev == NBLK - 1) ? 1u : 0u;
    }
    __syncthreads();
    if (slast){
        float a = -1e30f;
        if (t < Ln) a = g_alpha[t] + emit[t];      // + emit[0,0,:]
        float m = a;
        #pragma unroll
        for (int o = 16; o; o >>= 1) m = fmaxf(m, __shfl_xor_sync(0xffffffffu, m, o));
        if ((t & 31) == 0) red[t >> 5] = m;
        __syncthreads();
        m = fmaxf(fmaxf(fmaxf(red[0], red[1]), fmaxf(red[2], red[3])),
                  fmaxf(fmaxf(red[4], red[5]), fmaxf(red[6], red[7])));
        float e = (t < Ln) ? ex2f((a - m) * LOG2E) : 0.f;
        #pragma unroll
        for (int o = 16; o; o >>= 1) e += __shfl_xor_sync(0xffffffffu, e, o);
        if ((t & 31) == 0) red[8 + (t >> 5)] = e;
        __syncthreads();
        if (t == 0){
            float es = 0.f;
            #pragma unroll
            for (int i = 0; i < 8; ++i) es += red[8 + i];
            double logZ = (double)m + (double)(LN2f * lg2f_(es));
            out[0] = (float)((logZ - g_score) / (double)Bn);
        }
        __syncthreads();
        if (t < Ln)  g_alpha[t] = 0.0f;
        if (t == 0){ g_score = 0.0; g_done = 0u; }
    }
}

// ---------------------------------------------------------------------------
extern "C" void kernel_launch(void* const* d_in, const int* in_sizes, int n_in,
                              void* d_out, int out_size)
{
    const float* emit   = (const float*)d_in[0];
    const int*   labels = (const int*)d_in[1];
    const int*   mask   = (const int*)d_in[2];
    const float* trans  = (const float*)d_in[3];
    const float* strans = (const float*)d_in[4];
    const float* etrans = (const float*)d_in[5];
    float* out = (float*)d_out;

    mega_kernel<<<NBLK, 256>>>(emit, labels, mask, trans, strans, etrans, out);
}